// round 6
// baseline (speedup 1.0000x reference)
#include <cuda_runtime.h>

#define BB 2
#define NF 16
#define HH 512
#define WW 512
#define H2 1024
#define W2 1024
#define CINc 50
#define HW (HH*WW)
#define HW2 (H2*W2)

// tiles: 16x16 outputs at 512-res
#define TSW 16
#define TWW 34             // 2*TSW+2
#define TWNW (TWW*TWW)     // 1156
#define NPOS 5             // ceil(TWNW/256)

// -------- scratch (device globals; referenced ONLY from device code) --------
__device__ float  g_up16 [(size_t)BB*NF*HW2];  // upsampled tgt, planar
__device__ float  g_warped[(size_t)BB*NF*HW];  // warped tgt @512, planar
__device__ float  g_adj  [(size_t)BB*2*HW];    // conv output, planar
__device__ float  g_newres[(size_t)BB*2*HW];   // combined residual, planar
__device__ float2 g_a1024[(size_t)BB*HW2];     // up(res)*2, interleaved
__device__ float2 g_b1024[(size_t)BB*HW2];     // up(adj)*2
__device__ float2 g_nr1024[(size_t)BB*HW2];    // up(new_res)*2

// -------- resize helpers (jax.image.resize bilinear; validated R1) --------
__device__ __forceinline__ void up_taps(int i, int n_in, int& t0, int& t1,
                                        float& w0, float& w1) {
    int k = i >> 1;
    if ((i & 1) == 0) { t0 = k - 1; t1 = k;     w0 = 0.25f; w1 = 0.75f; }
    else              { t0 = k;     t1 = k + 1; w0 = 0.75f; w1 = 0.25f; }
    if (t0 < 0)     { t0 = t1; w0 = 0.f; w1 = 1.f; }
    if (t1 >= n_in) { t1 = t0; w1 = 0.f; w0 = 1.f; }
}
__device__ __forceinline__ float dbase(int t) { return (t == 0 || t == 3) ? 0.25f : 0.75f; }

// -------- kernel 1: upsample tgt 512->1024, 4 cols/thread, float4 store --------
__global__ void __launch_bounds__(256) k_up_img(const float* __restrict__ x) {
    int idx = blockIdx.x * blockDim.x + threadIdx.x;
    if (idx >= BB * H2 * (W2 / 4)) return;
    int xq = idx & (W2 / 4 - 1);
    int yy = (idx >> 8) & (H2 - 1);
    int b  = idx >> 18;
    int m = 2 * xq;
    int mm1 = max(m - 1, 0), mp2 = min(m + 2, WW - 1);
    float a00 = (m == 0) ? 0.f : 0.25f,  a01 = (m == 0) ? 1.f : 0.75f;
    float a30 = (m == WW - 2) ? 1.f : 0.75f, a31 = (m == WW - 2) ? 0.f : 0.25f;
    int ty0, ty1; float wy0, wy1;
    up_taps(yy, HH, ty0, ty1, wy0, wy1);
    int r0 = ty0 * WW, r1 = ty1 * WW;

    const float* xb = x + ((size_t)b * 2 * NF + NF) * HW;
    float* ob = g_up16 + (size_t)b * NF * HW2 + (size_t)yy * W2 + 4 * xq;
    #pragma unroll
    for (int c = 0; c < NF; c++) {
        const float* p = xb + (size_t)c * HW;
        float s0 = p[r0 + mm1]   * wy0 + p[r1 + mm1]   * wy1;
        float s1 = p[r0 + m]     * wy0 + p[r1 + m]     * wy1;
        float s2 = p[r0 + m + 1] * wy0 + p[r1 + m + 1] * wy1;
        float s3 = p[r0 + mp2]   * wy0 + p[r1 + mp2]   * wy1;
        float4 o;
        o.x = a00 * s0 + a01 * s1;
        o.y = 0.75f * s1 + 0.25f * s2;
        o.z = 0.25f * s1 + 0.75f * s2;
        o.w = a30 * s2 + a31 * s3;
        *(float4*)(ob + (size_t)c * HW2) = o;
    }
}

// -------- kernel 2: upsample a 2ch 512 field ->1024, *2, interleaved float2 ----
// src_sel: 0=ext, 1=g_adj, 2=g_newres ; dst_sel: 0=g_a1024, 1=g_b1024, 2=g_nr1024
__global__ void __launch_bounds__(256) k_up_res(const float* __restrict__ ext,
                                                int src_sel, int dst_sel) {
    int idx = blockIdx.x * blockDim.x + threadIdx.x;
    if (idx >= BB * H2 * (W2 / 4)) return;
    int xq = idx & (W2 / 4 - 1);
    int yy = (idx >> 8) & (H2 - 1);
    int b  = idx >> 18;
    int m = 2 * xq;
    int mm1 = max(m - 1, 0), mp2 = min(m + 2, WW - 1);
    float a00 = (m == 0) ? 0.f : 0.25f,  a01 = (m == 0) ? 1.f : 0.75f;
    float a30 = (m == WW - 2) ? 1.f : 0.75f, a31 = (m == WW - 2) ? 0.f : 0.25f;
    int ty0, ty1; float wy0, wy1;
    up_taps(yy, HH, ty0, ty1, wy0, wy1);
    int r0 = ty0 * WW, r1 = ty1 * WW;

    const float* src = (src_sel == 0) ? ext : ((src_sel == 1) ? g_adj : g_newres);
    const float* p0 = src + (size_t)b * 2 * HW;
    const float* p1 = p0 + HW;
    float ox[4], oy[4];
    {
        float s0 = p0[r0 + mm1]   * wy0 + p0[r1 + mm1]   * wy1;
        float s1 = p0[r0 + m]     * wy0 + p0[r1 + m]     * wy1;
        float s2 = p0[r0 + m + 1] * wy0 + p0[r1 + m + 1] * wy1;
        float s3 = p0[r0 + mp2]   * wy0 + p0[r1 + mp2]   * wy1;
        ox[0] = a00 * s0 + a01 * s1;  ox[1] = 0.75f * s1 + 0.25f * s2;
        ox[2] = 0.25f * s1 + 0.75f * s2;  ox[3] = a30 * s2 + a31 * s3;
    }
    {
        float s0 = p1[r0 + mm1]   * wy0 + p1[r1 + mm1]   * wy1;
        float s1 = p1[r0 + m]     * wy0 + p1[r1 + m]     * wy1;
        float s2 = p1[r0 + m + 1] * wy0 + p1[r1 + m + 1] * wy1;
        float s3 = p1[r0 + mp2]   * wy0 + p1[r1 + mp2]   * wy1;
        oy[0] = a00 * s0 + a01 * s1;  oy[1] = 0.75f * s1 + 0.25f * s2;
        oy[2] = 0.25f * s1 + 0.75f * s2;  oy[3] = a30 * s2 + a31 * s3;
    }
    float2* dst = (dst_sel == 0) ? g_a1024 : ((dst_sel == 1) ? g_b1024 : g_nr1024);
    float4* ob = (float4*)(dst + (size_t)b * HW2 + (size_t)yy * W2 + 4 * xq);
    ob[0] = make_float4(2.f * ox[0], 2.f * oy[0], 2.f * ox[1], 2.f * oy[1]);
    ob[1] = make_float4(2.f * ox[2], 2.f * oy[2], 2.f * ox[3], 2.f * oy[3]);
}

// -------- fused: read field1024 -> reg gather tables -> 16ch warp+downsample ----
// field_sel: 0 = g_a1024, 1 = g_nr1024 ; to_final: 0 -> g_warped, 1 -> out[16..31]
__global__ void __launch_bounds__(256) k_warpdown(
        float* __restrict__ out, int field_sel, int to_final) {
    __shared__ float s_w[TWNW];
    int b = blockIdx.z;
    int x0 = blockIdx.x * TSW, y0 = blockIdx.y * TSW;
    int gx0 = 2 * x0 - 1, gy0 = 2 * y0 - 1;
    int tid = threadIdx.x;

    const float2* fld = ((field_sel == 0) ? g_a1024 : g_nr1024) + (size_t)b * HW2;

    // ---- setup: gather geometry once per 1024-pos, kept in registers ----
    float4   rw[NPOS];
    unsigned rpk[NPOS];
    #pragma unroll
    for (int k = 0; k < NPOS; k++) {
        int i = tid + 256 * k;
        if (i < TWNW) {
            int r = i / TWW, cc = i - r * TWW;
            int Y = min(max(gy0 + r, 0), H2 - 1);
            int X = min(max(gx0 + cc, 0), W2 - 1);
            float2 f = fld[Y * W2 + X];
            float sx = (float)(gx0 + cc) + f.x;
            float sy = (float)(gy0 + r) + f.y;
            float xf = floorf(sx), yf = floorf(sy);
            float fx = sx - xf, fy = sy - yf;
            int ix0 = (int)xf, iy0 = (int)yf;
            bool bx0 = (unsigned)ix0 < W2, bx1 = (unsigned)(ix0 + 1) < W2;
            bool by0 = (unsigned)iy0 < H2, by1 = (unsigned)(iy0 + 1) < H2;
            float wx0 = bx0 ? (1.f - fx) : 0.f, wx1 = bx1 ? fx : 0.f;
            float wy0 = by0 ? (1.f - fy) : 0.f, wy1 = by1 ? fy : 0.f;
            rw[k] = make_float4(wy0 * wx0, wy0 * wx1, wy1 * wx0, wy1 * wx1);
            int cx0 = min(max(ix0, 0), W2 - 1), cx1 = min(max(ix0 + 1, 0), W2 - 1);
            int cy0 = min(max(iy0, 0), H2 - 1), cy1 = min(max(iy0 + 1, 0), H2 - 1);
            rpk[k] = (unsigned)(cy0 * W2 + cx0)
                   | ((unsigned)(cx1 - cx0) << 20)
                   | ((unsigned)(cy1 - cy0) << 21);
        }
    }

    const float* img = g_up16 + (size_t)b * NF * HW2;
    float* dstb = to_final ? (out + ((size_t)b * 2 * NF + NF) * HW)
                           : (g_warped + (size_t)b * NF * HW);
    int lx = tid & (TSW - 1), ly = tid >> 4;   // one output pixel per thread
    int yy = y0 + ly, xx = x0 + lx;
    float invsy = (yy == 0 || yy == HH - 1) ? (1.f / 1.75f) : 0.5f;
    float invsx = (xx == 0 || xx == WW - 1) ? (1.f / 1.75f) : 0.5f;
    float wyv[4], wxv[4];
    #pragma unroll
    for (int t = 0; t < 4; t++) {
        wyv[t] = ((unsigned)(gy0 + 2 * ly + t) < H2) ? dbase(t) * invsy : 0.f;
        wxv[t] = ((unsigned)(gx0 + 2 * lx + t) < W2) ? dbase(t) * invsx : 0.f;
    }
    int sbase = (2 * ly) * TWW + 2 * lx;

    for (int c = 0; c < NF; c++) {
        const float* p = img + (size_t)c * HW2;
        #pragma unroll
        for (int k = 0; k < NPOS; k++) {
            int i = tid + 256 * k;
            if (i < TWNW) {
                unsigned pk = rpk[k];
                float4 w = rw[k];
                int o00 = (int)(pk & 0xFFFFFu);
                int dx  = (int)((pk >> 20) & 1u);
                int o10 = o00 + (int)((pk >> 11) & 1024u);
                s_w[i] = w.x * p[o00] + w.y * p[o00 + dx]
                       + w.z * p[o10] + w.w * p[o10 + dx];
            }
        }
        __syncthreads();
        float acc = 0.f;
        #pragma unroll
        for (int ty = 0; ty < 4; ty++) {
            const float* sr = s_w + sbase + ty * TWW;
            acc += wyv[ty] * (wxv[0] * sr[0] + wxv[1] * sr[1]
                            + wxv[2] * sr[2] + wxv[3] * sr[3]);
        }
        dstb[(size_t)c * HW + yy * WW + xx] = acc;
        __syncthreads();
    }
}

// -------- 3x3 conv 50->2 (4 outputs/thread) + float4 pass-through --------
__global__ void __launch_bounds__(256) k_conv(
        const float* __restrict__ x, const float* __restrict__ res,
        const float* __restrict__ Wc, const float* __restrict__ bias,
        float* __restrict__ out) {
    __shared__ float sw[2 * CINc * 9];
    for (int i = threadIdx.x; i < 2 * CINc * 9; i += blockDim.x) sw[i] = Wc[i];
    __syncthreads();
    int idx = blockIdx.x * blockDim.x + threadIdx.x;
    if (idx >= BB * HH * (WW / 4)) return;
    int xq = idx & (WW / 4 - 1);
    int yy = (idx >> 7) & (HH - 1);
    int b  = idx >> 16;
    int xx0 = 4 * xq;
    float a0[4], a1[4];
    #pragma unroll
    for (int o = 0; o < 4; o++) { a0[o] = bias[0]; a1[o] = bias[1]; }

    const float* xb = x + (size_t)b * 2 * NF * HW;
    const float* wb = g_warped + (size_t)b * NF * HW;
    const float* rb = res + (size_t)b * 2 * HW;
    bool lok = (xq > 0), rok = (xq < WW / 4 - 1);

    #pragma unroll
    for (int dy = -1; dy <= 1; dy++) {
        int y2 = yy + dy;
        if ((unsigned)y2 >= HH) continue;
        int ro = y2 * WW + xx0;
        int kr = (dy + 1) * 3;
        // channels 0..47 from two planar sources
        #pragma unroll 4
        for (int c = 0; c < 48; c++) {
            const float* p = (c < 32) ? (xb + (size_t)c * HW)
                                      : (wb + (size_t)(c - 32) * HW);
            float l0 = lok ? p[ro - 1] : 0.f;
            float l1 = p[ro], l2 = p[ro + 1], l3 = p[ro + 2], l4 = p[ro + 3];
            float l5 = rok ? p[ro + 4] : 0.f;
            const float* w0 = sw + c * 9 + kr;
            const float* w1 = sw + CINc * 9 + c * 9 + kr;
            float q0 = w0[0], q1 = w0[1], q2 = w0[2];
            float u0 = w1[0], u1 = w1[1], u2 = w1[2];
            a0[0] += l0 * q0 + l1 * q1 + l2 * q2;
            a0[1] += l1 * q0 + l2 * q1 + l3 * q2;
            a0[2] += l2 * q0 + l3 * q1 + l4 * q2;
            a0[3] += l3 * q0 + l4 * q1 + l5 * q2;
            a1[0] += l0 * u0 + l1 * u1 + l2 * u2;
            a1[1] += l1 * u0 + l2 * u1 + l3 * u2;
            a1[2] += l2 * u0 + l3 * u1 + l4 * u2;
            a1[3] += l3 * u0 + l4 * u1 + l5 * u2;
        }
        // residual channels 48,49
        #pragma unroll
        for (int c = 0; c < 2; c++) {
            const float* p = rb + (size_t)c * HW;
            float l0 = lok ? p[ro - 1] : 0.f;
            float l1 = p[ro], l2 = p[ro + 1], l3 = p[ro + 2], l4 = p[ro + 3];
            float l5 = rok ? p[ro + 4] : 0.f;
            const float* w0 = sw + (48 + c) * 9 + kr;
            const float* w1 = sw + CINc * 9 + (48 + c) * 9 + kr;
            float q0 = w0[0], q1 = w0[1], q2 = w0[2];
            float u0 = w1[0], u1 = w1[1], u2 = w1[2];
            a0[0] += l0 * q0 + l1 * q1 + l2 * q2;
            a0[1] += l1 * q0 + l2 * q1 + l3 * q2;
            a0[2] += l2 * q0 + l3 * q1 + l4 * q2;
            a0[3] += l3 * q0 + l4 * q1 + l5 * q2;
            a1[0] += l0 * u0 + l1 * u1 + l2 * u2;
            a1[1] += l1 * u0 + l2 * u1 + l3 * u2;
            a1[2] += l2 * u0 + l3 * u1 + l4 * u2;
            a1[3] += l3 * u0 + l4 * u1 + l5 * u2;
        }
    }
    int pc = yy * WW + xx0;
    float* o = g_adj + (size_t)b * 2 * HW + pc;
    *(float4*)o        = make_float4(a0[0], a0[1], a0[2], a0[3]);
    *(float4*)(o + HW) = make_float4(a1[0], a1[1], a1[2], a1[3]);
    // pass-through: out[b][0..15] = x[b][0..15]
    float* ob = out + (size_t)b * 2 * NF * HW + pc;
    #pragma unroll
    for (int c = 0; c < NF; c++)
        *(float4*)(ob + (size_t)c * HW) = *(const float4*)(xb + (size_t)c * HW + pc);
}

// -------- fused: warp a1024 by b1024 (tables) -> downsample*0.5 + adj ----------
__global__ void __launch_bounds__(256) k_combine() {
    __shared__ float2 s_w[TWNW];
    int b = blockIdx.z;
    int x0 = blockIdx.x * TSW, y0 = blockIdx.y * TSW;
    int gx0 = 2 * x0 - 1, gy0 = 2 * y0 - 1;
    int tid = threadIdx.x;

    const float2* bf = g_b1024 + (size_t)b * HW2;
    const float2* af = g_a1024 + (size_t)b * HW2;

    float4   rw[NPOS];
    unsigned rpk[NPOS];
    #pragma unroll
    for (int k = 0; k < NPOS; k++) {
        int i = tid + 256 * k;
        if (i < TWNW) {
            int r = i / TWW, cc = i - r * TWW;
            int Y = min(max(gy0 + r, 0), H2 - 1);
            int X = min(max(gx0 + cc, 0), W2 - 1);
            float2 f = bf[Y * W2 + X];
            float sx = (float)(gx0 + cc) + f.x;
            float sy = (float)(gy0 + r) + f.y;
            float xf = floorf(sx), yf = floorf(sy);
            float fx = sx - xf, fy = sy - yf;
            int ix0 = (int)xf, iy0 = (int)yf;
            bool bx0 = (unsigned)ix0 < W2, bx1 = (unsigned)(ix0 + 1) < W2;
            bool by0 = (unsigned)iy0 < H2, by1 = (unsigned)(iy0 + 1) < H2;
            float wx0 = bx0 ? (1.f - fx) : 0.f, wx1 = bx1 ? fx : 0.f;
            float wy0 = by0 ? (1.f - fy) : 0.f, wy1 = by1 ? fy : 0.f;
            rw[k] = make_float4(wy0 * wx0, wy0 * wx1, wy1 * wx0, wy1 * wx1);
            int cx0 = min(max(ix0, 0), W2 - 1), cx1 = min(max(ix0 + 1, 0), W2 - 1);
            int cy0 = min(max(iy0, 0), H2 - 1), cy1 = min(max(iy0 + 1, 0), H2 - 1);
            rpk[k] = (unsigned)(cy0 * W2 + cx0)
                   | ((unsigned)(cx1 - cx0) << 20)
                   | ((unsigned)(cy1 - cy0) << 21);
        }
    }

    #pragma unroll
    for (int k = 0; k < NPOS; k++) {
        int i = tid + 256 * k;
        if (i < TWNW) {
            unsigned pk = rpk[k];
            float4 w = rw[k];
            int o00 = (int)(pk & 0xFFFFFu);
            int dx  = (int)((pk >> 20) & 1u);
            int o10 = o00 + (int)((pk >> 11) & 1024u);
            float2 v00 = af[o00], v01 = af[o00 + dx];
            float2 v10 = af[o10], v11 = af[o10 + dx];
            s_w[i] = make_float2(
                w.x * v00.x + w.y * v01.x + w.z * v10.x + w.w * v11.x,
                w.x * v00.y + w.y * v01.y + w.z * v10.y + w.w * v11.y);
        }
    }
    __syncthreads();

    int lx = tid & (TSW - 1), ly = tid >> 4;
    int yy = y0 + ly, xx = x0 + lx;
    float invsy = (yy == 0 || yy == HH - 1) ? (1.f / 1.75f) : 0.5f;
    float invsx = (xx == 0 || xx == WW - 1) ? (1.f / 1.75f) : 0.5f;
    float wyv[4], wxv[4];
    #pragma unroll
    for (int t = 0; t < 4; t++) {
        wyv[t] = ((unsigned)(gy0 + 2 * ly + t) < H2) ? dbase(t) * invsy : 0.f;
        wxv[t] = ((unsigned)(gx0 + 2 * lx + t) < W2) ? dbase(t) * invsx : 0.f;
    }
    int sbase = (2 * ly) * TWW + 2 * lx;
    float accx = 0.f, accy = 0.f;
    #pragma unroll
    for (int ty = 0; ty < 4; ty++) {
        const float2* sr = s_w + sbase + ty * TWW;
        float rx = wxv[0] * sr[0].x + wxv[1] * sr[1].x + wxv[2] * sr[2].x + wxv[3] * sr[3].x;
        float ry = wxv[0] * sr[0].y + wxv[1] * sr[1].y + wxv[2] * sr[2].y + wxv[3] * sr[3].y;
        accx += wyv[ty] * rx;
        accy += wyv[ty] * ry;
    }
    int p = yy * WW + xx;
    const float* ad = g_adj + (size_t)b * 2 * HW;
    float* nr = g_newres + (size_t)b * 2 * HW;
    nr[p]      = ad[p]      + 0.5f * accx;
    nr[HW + p] = ad[HW + p] + 0.5f * accy;
}

// -------- launch --------
extern "C" void kernel_launch(void* const* d_in, const int* in_sizes, int n_in,
                              void* d_out, int out_size) {
    const float* x    = (const float*)d_in[0];
    const float* res  = (const float*)d_in[1];
    const float* Wc   = (const float*)d_in[2];
    const float* bias = (const float*)d_in[3];
    float* out = (float*)d_out;

    const int T = 256;
    dim3 gu((BB * H2 * (W2 / 4) + T - 1) / T);
    dim3 gcv((BB * HH * (WW / 4) + T - 1) / T);
    dim3 gw(HH / TSW, WW / TSW, BB);   // 32 x 32 x 2 tiles

    k_up_img<<<gu, T>>>(x);                       // tgt -> g_up16
    k_up_res<<<gu, T>>>(res, 0, 0);               // res -> g_a1024 (*2)
    k_warpdown<<<gw, T>>>(nullptr, 0, 0);         // warp by a1024 -> g_warped
    k_conv<<<gcv, T>>>(x, res, Wc, bias, out);    // adj + src pass-through
    k_up_res<<<gu, T>>>(nullptr, 1, 1);           // adj -> g_b1024 (*2)
    k_combine<<<gw, T>>>();                       // -> g_newres
    k_up_res<<<gu, T>>>(nullptr, 2, 2);           // new_res -> g_nr1024 (*2)
    k_warpdown<<<gw, T>>>(out, 1, 1);             // warp by nr1024 -> out[16..31]
}

// round 7
// speedup vs baseline: 1.1809x; 1.1809x over previous
#include <cuda_runtime.h>

#define BB 2
#define NF 16
#define NG 4               // channel groups of 4 (float4)
#define HH 512
#define WW 512
#define H2 1024
#define W2 1024
#define CINc 50
#define HW (HH*WW)
#define HW2 (H2*W2)

// tiles: 16x16 outputs at 512-res
#define TSW 16
#define TWW 34             // 2*TSW+2
#define TWNW (TWW*TWW)     // 1156
#define NPOS 5             // ceil(TWNW/256)

// -------- scratch (device globals; referenced ONLY from device code) --------
__device__ float4 g_up16 [(size_t)BB*NG*HW2];  // upsampled tgt, channel-packed x4
__device__ float  g_warped[(size_t)BB*NF*HW];  // warped tgt @512, planar
__device__ float  g_adj  [(size_t)BB*2*HW];    // conv output, planar
__device__ float  g_newres[(size_t)BB*2*HW];   // combined residual, planar
__device__ float2 g_a1024[(size_t)BB*HW2];     // up(res)*2, interleaved
__device__ float2 g_b1024[(size_t)BB*HW2];     // up(adj)*2
__device__ float2 g_nr1024[(size_t)BB*HW2];    // up(new_res)*2

// -------- resize helpers (jax.image.resize bilinear; validated R1) --------
__device__ __forceinline__ void up_taps(int i, int n_in, int& t0, int& t1,
                                        float& w0, float& w1) {
    int k = i >> 1;
    if ((i & 1) == 0) { t0 = k - 1; t1 = k;     w0 = 0.25f; w1 = 0.75f; }
    else              { t0 = k;     t1 = k + 1; w0 = 0.75f; w1 = 0.25f; }
    if (t0 < 0)     { t0 = t1; w0 = 0.f; w1 = 1.f; }
    if (t1 >= n_in) { t1 = t0; w1 = 0.f; w0 = 1.f; }
}
__device__ __forceinline__ float dbase(int t) { return (t == 0 || t == 3) ? 0.25f : 0.75f; }

// -------- kernel 1: upsample tgt 512->1024 into channel-packed float4 --------
// one thread per (b, y1024, x1024); writes NG float4s (coalesced 16B/lane).
__global__ void __launch_bounds__(256) k_up_img(const float* __restrict__ x) {
    int idx = blockIdx.x * blockDim.x + threadIdx.x;
    if (idx >= BB * HW2) return;
    int xx = idx & (W2 - 1), yy = (idx >> 10) & (H2 - 1), b = idx >> 20;
    int ty0, ty1, tx0, tx1; float wy0, wy1, wx0, wx1;
    up_taps(yy, HH, ty0, ty1, wy0, wy1);
    up_taps(xx, WW, tx0, tx1, wx0, wx1);
    int r0 = ty0 * WW, r1 = ty1 * WW;
    float w00 = wy0 * wx0, w01 = wy0 * wx1, w10 = wy1 * wx0, w11 = wy1 * wx1;

    const float* xb = x + ((size_t)b * 2 * NF + NF) * HW;
    float4* ob = g_up16 + (size_t)b * NG * HW2 + (size_t)yy * W2 + xx;
    #pragma unroll
    for (int g = 0; g < NG; g++) {
        float4 o;
        float* oo = (float*)&o;
        #pragma unroll
        for (int j = 0; j < 4; j++) {
            const float* p = xb + (size_t)(4 * g + j) * HW;
            oo[j] = w00 * p[r0 + tx0] + w01 * p[r0 + tx1]
                  + w10 * p[r1 + tx0] + w11 * p[r1 + tx1];
        }
        ob[(size_t)g * HW2] = o;
    }
}

// -------- kernel 2: upsample a 2ch 512 field ->1024, *2, interleaved float2 ----
__global__ void __launch_bounds__(256) k_up_res(const float* __restrict__ ext,
                                                int src_sel, int dst_sel) {
    int idx = blockIdx.x * blockDim.x + threadIdx.x;
    if (idx >= BB * H2 * (W2 / 4)) return;
    int xq = idx & (W2 / 4 - 1);
    int yy = (idx >> 8) & (H2 - 1);
    int b  = idx >> 18;
    int m = 2 * xq;
    int mm1 = max(m - 1, 0), mp2 = min(m + 2, WW - 1);
    float a00 = (m == 0) ? 0.f : 0.25f,  a01 = (m == 0) ? 1.f : 0.75f;
    float a30 = (m == WW - 2) ? 1.f : 0.75f, a31 = (m == WW - 2) ? 0.f : 0.25f;
    int ty0, ty1; float wy0, wy1;
    up_taps(yy, HH, ty0, ty1, wy0, wy1);
    int r0 = ty0 * WW, r1 = ty1 * WW;

    const float* src = (src_sel == 0) ? ext : ((src_sel == 1) ? g_adj : g_newres);
    const float* p0 = src + (size_t)b * 2 * HW;
    const float* p1 = p0 + HW;
    float ox[4], oy[4];
    {
        float s0 = p0[r0 + mm1]   * wy0 + p0[r1 + mm1]   * wy1;
        float s1 = p0[r0 + m]     * wy0 + p0[r1 + m]     * wy1;
        float s2 = p0[r0 + m + 1] * wy0 + p0[r1 + m + 1] * wy1;
        float s3 = p0[r0 + mp2]   * wy0 + p0[r1 + mp2]   * wy1;
        ox[0] = a00 * s0 + a01 * s1;  ox[1] = 0.75f * s1 + 0.25f * s2;
        ox[2] = 0.25f * s1 + 0.75f * s2;  ox[3] = a30 * s2 + a31 * s3;
    }
    {
        float s0 = p1[r0 + mm1]   * wy0 + p1[r1 + mm1]   * wy1;
        float s1 = p1[r0 + m]     * wy0 + p1[r1 + m]     * wy1;
        float s2 = p1[r0 + m + 1] * wy0 + p1[r1 + m + 1] * wy1;
        float s3 = p1[r0 + mp2]   * wy0 + p1[r1 + mp2]   * wy1;
        oy[0] = a00 * s0 + a01 * s1;  oy[1] = 0.75f * s1 + 0.25f * s2;
        oy[2] = 0.25f * s1 + 0.75f * s2;  oy[3] = a30 * s2 + a31 * s3;
    }
    float2* dst = (dst_sel == 0) ? g_a1024 : ((dst_sel == 1) ? g_b1024 : g_nr1024);
    float4* ob = (float4*)(dst + (size_t)b * HW2 + (size_t)yy * W2 + 4 * xq);
    ob[0] = make_float4(2.f * ox[0], 2.f * oy[0], 2.f * ox[1], 2.f * oy[1]);
    ob[1] = make_float4(2.f * ox[2], 2.f * oy[2], 2.f * ox[3], 2.f * oy[3]);
}

// -------- fused: reg gather tables -> 4ch-at-a-time warp+downsample --------
// field_sel: 0 = g_a1024, 1 = g_nr1024 ; to_final: 0 -> g_warped, 1 -> out[16..31]
__global__ void __launch_bounds__(256) k_warpdown(
        float* __restrict__ out, int field_sel, int to_final) {
    __shared__ float4 s_w[TWNW];        // warped values for current 4-ch group
    int b = blockIdx.z;
    int x0 = blockIdx.x * TSW, y0 = blockIdx.y * TSW;
    int gx0 = 2 * x0 - 1, gy0 = 2 * y0 - 1;
    int tid = threadIdx.x;

    const float2* fld = ((field_sel == 0) ? g_a1024 : g_nr1024) + (size_t)b * HW2;

    // ---- setup: gather geometry once per 1024-pos, in registers ----
    float4   rw[NPOS];
    unsigned rpk[NPOS];
    #pragma unroll
    for (int k = 0; k < NPOS; k++) {
        int i = tid + 256 * k;
        if (i < TWNW) {
            int r = i / TWW, cc = i - r * TWW;
            int Y = min(max(gy0 + r, 0), H2 - 1);
            int X = min(max(gx0 + cc, 0), W2 - 1);
            float2 f = fld[Y * W2 + X];
            float sx = (float)(gx0 + cc) + f.x;
            float sy = (float)(gy0 + r) + f.y;
            float xf = floorf(sx), yf = floorf(sy);
            float fx = sx - xf, fy = sy - yf;
            int ix0 = (int)xf, iy0 = (int)yf;
            bool bx0 = (unsigned)ix0 < W2, bx1 = (unsigned)(ix0 + 1) < W2;
            bool by0 = (unsigned)iy0 < H2, by1 = (unsigned)(iy0 + 1) < H2;
            float wx0 = bx0 ? (1.f - fx) : 0.f, wx1 = bx1 ? fx : 0.f;
            float wy0 = by0 ? (1.f - fy) : 0.f, wy1 = by1 ? fy : 0.f;
            rw[k] = make_float4(wy0 * wx0, wy0 * wx1, wy1 * wx0, wy1 * wx1);
            int cx0 = min(max(ix0, 0), W2 - 1), cx1 = min(max(ix0 + 1, 0), W2 - 1);
            int cy0 = min(max(iy0, 0), H2 - 1), cy1 = min(max(iy0 + 1, 0), H2 - 1);
            rpk[k] = (unsigned)(cy0 * W2 + cx0)
                   | ((unsigned)(cx1 - cx0) << 20)
                   | ((unsigned)(cy1 - cy0) << 21);
        }
    }

    const float4* img = g_up16 + (size_t)b * NG * HW2;
    float* dstb = to_final ? (out + ((size_t)b * 2 * NF + NF) * HW)
                           : (g_warped + (size_t)b * NF * HW);
    int lx = tid & (TSW - 1), ly = tid >> 4;   // one output pixel per thread
    int yy = y0 + ly, xx = x0 + lx;
    float invsy = (yy == 0 || yy == HH - 1) ? (1.f / 1.75f) : 0.5f;
    float invsx = (xx == 0 || xx == WW - 1) ? (1.f / 1.75f) : 0.5f;
    float wyv[4], wxv[4];
    #pragma unroll
    for (int t = 0; t < 4; t++) {
        wyv[t] = ((unsigned)(gy0 + 2 * ly + t) < H2) ? dbase(t) * invsy : 0.f;
        wxv[t] = ((unsigned)(gx0 + 2 * lx + t) < W2) ? dbase(t) * invsx : 0.f;
    }
    int sbase = (2 * ly) * TWW + 2 * lx;
    int opix = yy * WW + xx;

    for (int g = 0; g < NG; g++) {
        const float4* p = img + (size_t)g * HW2;
        #pragma unroll
        for (int k = 0; k < NPOS; k++) {
            int i = tid + 256 * k;
            if (i < TWNW) {
                unsigned pk = rpk[k];
                float4 w = rw[k];
                int o00 = (int)(pk & 0xFFFFFu);
                int dx  = (int)((pk >> 20) & 1u);
                int o10 = o00 + (int)((pk >> 11) & 1024u);
                float4 v00 = p[o00], v01 = p[o00 + dx];
                float4 v10 = p[o10], v11 = p[o10 + dx];
                float4 acc;
                acc.x = w.x * v00.x + w.y * v01.x + w.z * v10.x + w.w * v11.x;
                acc.y = w.x * v00.y + w.y * v01.y + w.z * v10.y + w.w * v11.y;
                acc.z = w.x * v00.z + w.y * v01.z + w.z * v10.z + w.w * v11.z;
                acc.w = w.x * v00.w + w.y * v01.w + w.z * v10.w + w.w * v11.w;
                s_w[i] = acc;
            }
        }
        __syncthreads();
        float4 acc = make_float4(0.f, 0.f, 0.f, 0.f);
        #pragma unroll
        for (int ty = 0; ty < 4; ty++) {
            const float4* sr = s_w + sbase + ty * TWW;
            float4 rowv = make_float4(0.f, 0.f, 0.f, 0.f);
            #pragma unroll
            for (int tx = 0; tx < 4; tx++) {
                float4 v = sr[tx];
                float w = wxv[tx];
                rowv.x += w * v.x; rowv.y += w * v.y;
                rowv.z += w * v.z; rowv.w += w * v.w;
            }
            float w = wyv[ty];
            acc.x += w * rowv.x; acc.y += w * rowv.y;
            acc.z += w * rowv.z; acc.w += w * rowv.w;
        }
        dstb[(size_t)(4 * g + 0) * HW + opix] = acc.x;
        dstb[(size_t)(4 * g + 1) * HW + opix] = acc.y;
        dstb[(size_t)(4 * g + 2) * HW + opix] = acc.z;
        dstb[(size_t)(4 * g + 3) * HW + opix] = acc.w;
        __syncthreads();
    }
}

// -------- 3x3 conv 50->2 (R5 version) + pass-through of src channels ----------
__global__ void __launch_bounds__(256) k_conv(
        const float* __restrict__ x, const float* __restrict__ res,
        const float* __restrict__ Wc, const float* __restrict__ bias,
        float* __restrict__ out) {
    __shared__ float sw[2 * CINc * 9];
    for (int i = threadIdx.x; i < 2 * CINc * 9; i += blockDim.x) sw[i] = Wc[i];
    __syncthreads();
    int idx = blockIdx.x * blockDim.x + threadIdx.x;
    if (idx >= BB * HW) return;
    int xx = idx & (WW - 1), yy = (idx >> 9) & (HH - 1), b = idx >> 18;
    float a0 = bias[0], a1 = bias[1];
    const float* xb = x + (size_t)b * 2 * NF * HW;
    const float* wb = g_warped + (size_t)b * NF * HW;
    const float* rb = res + (size_t)b * 2 * HW;
    for (int dy = -1; dy <= 1; dy++) {
        int y2 = yy + dy;
        if ((unsigned)y2 >= HH) continue;
        for (int dx = -1; dx <= 1; dx++) {
            int x2 = xx + dx;
            if ((unsigned)x2 >= WW) continue;
            int kidx = (dy + 1) * 3 + (dx + 1);
            int p = y2 * WW + x2;
            const float* s0 = sw + kidx;
            const float* s1 = sw + CINc * 9 + kidx;
            #pragma unroll 8
            for (int c = 0; c < 32; c++) {
                float v = xb[(size_t)c * HW + p];
                a0 += v * s0[c * 9];
                a1 += v * s1[c * 9];
            }
            #pragma unroll 8
            for (int c = 0; c < 16; c++) {
                float v = wb[(size_t)c * HW + p];
                a0 += v * s0[(32 + c) * 9];
                a1 += v * s1[(32 + c) * 9];
            }
            float v0 = rb[p], v1 = rb[HW + p];
            a0 += v0 * s0[48 * 9] + v1 * s0[49 * 9];
            a1 += v0 * s1[48 * 9] + v1 * s1[49 * 9];
        }
    }
    int pc = yy * WW + xx;
    float* o = g_adj + (size_t)b * 2 * HW + pc;
    o[0] = a0;
    o[HW] = a1;
    float* ob = out + (size_t)b * 2 * NF * HW + pc;
    #pragma unroll
    for (int c = 0; c < NF; c++) ob[(size_t)c * HW] = xb[(size_t)c * HW + pc];
}

// -------- fused: warp a1024 by b1024 (tables) -> downsample*0.5 + adj ----------
__global__ void __launch_bounds__(256) k_combine() {
    __shared__ float2 s_w[TWNW];
    int b = blockIdx.z;
    int x0 = blockIdx.x * TSW, y0 = blockIdx.y * TSW;
    int gx0 = 2 * x0 - 1, gy0 = 2 * y0 - 1;
    int tid = threadIdx.x;

    const float2* bf = g_b1024 + (size_t)b * HW2;
    const float2* af = g_a1024 + (size_t)b * HW2;

    #pragma unroll
    for (int k = 0; k < NPOS; k++) {
        int i = tid + 256 * k;
        if (i < TWNW) {
            int r = i / TWW, cc = i - r * TWW;
            int Y = min(max(gy0 + r, 0), H2 - 1);
            int X = min(max(gx0 + cc, 0), W2 - 1);
            float2 f = bf[Y * W2 + X];
            float sx = (float)(gx0 + cc) + f.x;
            float sy = (float)(gy0 + r) + f.y;
            float xf = floorf(sx), yf = floorf(sy);
            float fx = sx - xf, fy = sy - yf;
            int ix0 = (int)xf, iy0 = (int)yf;
            bool bx0 = (unsigned)ix0 < W2, bx1 = (unsigned)(ix0 + 1) < W2;
            bool by0 = (unsigned)iy0 < H2, by1 = (unsigned)(iy0 + 1) < H2;
            float wx0 = bx0 ? (1.f - fx) : 0.f, wx1 = bx1 ? fx : 0.f;
            float wy0 = by0 ? (1.f - fy) : 0.f, wy1 = by1 ? fy : 0.f;
            float w00 = wy0 * wx0, w01 = wy0 * wx1, w10 = wy1 * wx0, w11 = wy1 * wx1;
            int cx0 = min(max(ix0, 0), W2 - 1), cx1 = min(max(ix0 + 1, 0), W2 - 1);
            int cy0 = min(max(iy0, 0), H2 - 1), cy1 = min(max(iy0 + 1, 0), H2 - 1);
            int o00 = cy0 * W2 + cx0;
            int dxo = cx1 - cx0;
            int o10 = o00 + (cy1 - cy0) * W2;
            float2 v00 = af[o00], v01 = af[o00 + dxo];
            float2 v10 = af[o10], v11 = af[o10 + dxo];
            s_w[i] = make_float2(
                w00 * v00.x + w01 * v01.x + w10 * v10.x + w11 * v11.x,
                w00 * v00.y + w01 * v01.y + w10 * v10.y + w11 * v11.y);
        }
    }
    __syncthreads();

    int lx = tid & (TSW - 1), ly = tid >> 4;
    int yy = y0 + ly, xx = x0 + lx;
    float invsy = (yy == 0 || yy == HH - 1) ? (1.f / 1.75f) : 0.5f;
    float invsx = (xx == 0 || xx == WW - 1) ? (1.f / 1.75f) : 0.5f;
    float wyv[4], wxv[4];
    #pragma unroll
    for (int t = 0; t < 4; t++) {
        wyv[t] = ((unsigned)(gy0 + 2 * ly + t) < H2) ? dbase(t) * invsy : 0.f;
        wxv[t] = ((unsigned)(gx0 + 2 * lx + t) < W2) ? dbase(t) * invsx : 0.f;
    }
    int sbase = (2 * ly) * TWW + 2 * lx;
    float accx = 0.f, accy = 0.f;
    #pragma unroll
    for (int ty = 0; ty < 4; ty++) {
        const float2* sr = s_w + sbase + ty * TWW;
        float rx = wxv[0] * sr[0].x + wxv[1] * sr[1].x + wxv[2] * sr[2].x + wxv[3] * sr[3].x;
        float ry = wxv[0] * sr[0].y + wxv[1] * sr[1].y + wxv[2] * sr[2].y + wxv[3] * sr[3].y;
        accx += wyv[ty] * rx;
        accy += wyv[ty] * ry;
    }
    int p = yy * WW + xx;
    const float* ad = g_adj + (size_t)b * 2 * HW;
    float* nr = g_newres + (size_t)b * 2 * HW;
    nr[p]      = ad[p]      + 0.5f * accx;
    nr[HW + p] = ad[HW + p] + 0.5f * accy;
}

// -------- launch --------
extern "C" void kernel_launch(void* const* d_in, const int* in_sizes, int n_in,
                              void* d_out, int out_size) {
    const float* x    = (const float*)d_in[0];
    const float* res  = (const float*)d_in[1];
    const float* Wc   = (const float*)d_in[2];
    const float* bias = (const float*)d_in[3];
    float* out = (float*)d_out;

    const int T = 256;
    dim3 gu1((BB * HW2 + T - 1) / T);
    dim3 gu((BB * H2 * (W2 / 4) + T - 1) / T);
    dim3 gcv((BB * HW + T - 1) / T);
    dim3 gw(HH / TSW, WW / TSW, BB);   // 32 x 32 x 2 tiles

    k_up_img<<<gu1, T>>>(x);                      // tgt -> g_up16 (packed x4)
    k_up_res<<<gu, T>>>(res, 0, 0);               // res -> g_a1024 (*2)
    k_warpdown<<<gw, T>>>(nullptr, 0, 0);         // warp by a1024 -> g_warped
    k_conv<<<gcv, T>>>(x, res, Wc, bias, out);    // adj + src pass-through
    k_up_res<<<gu, T>>>(nullptr, 1, 1);           // adj -> g_b1024 (*2)
    k_combine<<<gw, T>>>();                       // -> g_newres
    k_up_res<<<gu, T>>>(nullptr, 2, 2);           // new_res -> g_nr1024 (*2)
    k_warpdown<<<gw, T>>>(out, 1, 1);             // warp by nr1024 -> out[16..31]
}

// round 8
// speedup vs baseline: 1.2147x; 1.0286x over previous
#include <cuda_runtime.h>

#define BB 2
#define NF 16
#define NG 4               // channel groups of 4 (float4)
#define HH 512
#define WW 512
#define H2 1024
#define W2 1024
#define CINc 50
#define HW (HH*WW)
#define HW2 (H2*W2)

// warp/combine tiles: 16x16 outputs at 512-res
#define TSW 16
#define TWW 34             // 2*TSW+2
#define TWNW (TWW*TWW)     // 1156
#define NPOS 5             // ceil(TWNW/256)

// conv strip height
#define CR 8

// -------- scratch (device globals; referenced ONLY from device code) --------
__device__ float4 g_up16 [(size_t)BB*NG*HW2];  // upsampled tgt, channel-packed x4
__device__ float  g_warped[(size_t)BB*NF*HW];  // warped tgt @512, planar
__device__ float  g_adj  [(size_t)BB*2*HW];    // conv output, planar
__device__ float  g_newres[(size_t)BB*2*HW];   // combined residual, planar
__device__ float2 g_a1024[(size_t)BB*HW2];     // up(res)*2, interleaved
__device__ float2 g_b1024[(size_t)BB*HW2];     // up(adj)*2
__device__ float2 g_nr1024[(size_t)BB*HW2];    // up(new_res)*2

// -------- resize helpers (jax.image.resize bilinear; validated R1) --------
__device__ __forceinline__ void up_taps(int i, int n_in, int& t0, int& t1,
                                        float& w0, float& w1) {
    int k = i >> 1;
    if ((i & 1) == 0) { t0 = k - 1; t1 = k;     w0 = 0.25f; w1 = 0.75f; }
    else              { t0 = k;     t1 = k + 1; w0 = 0.75f; w1 = 0.25f; }
    if (t0 < 0)     { t0 = t1; w0 = 0.f; w1 = 1.f; }
    if (t1 >= n_in) { t1 = t0; w1 = 0.f; w0 = 1.f; }
}
__device__ __forceinline__ float dbase(int t) { return (t == 0 || t == 3) ? 0.25f : 0.75f; }

// -------- kernel 1: upsample tgt 512->1024 into channel-packed float4 --------
__global__ void __launch_bounds__(256) k_up_img(const float* __restrict__ x) {
    int idx = blockIdx.x * blockDim.x + threadIdx.x;
    if (idx >= BB * HW2) return;
    int xx = idx & (W2 - 1), yy = (idx >> 10) & (H2 - 1), b = idx >> 20;
    int ty0, ty1, tx0, tx1; float wy0, wy1, wx0, wx1;
    up_taps(yy, HH, ty0, ty1, wy0, wy1);
    up_taps(xx, WW, tx0, tx1, wx0, wx1);
    int r0 = ty0 * WW, r1 = ty1 * WW;
    float w00 = wy0 * wx0, w01 = wy0 * wx1, w10 = wy1 * wx0, w11 = wy1 * wx1;

    const float* xb = x + ((size_t)b * 2 * NF + NF) * HW;
    float4* ob = g_up16 + (size_t)b * NG * HW2 + (size_t)yy * W2 + xx;
    #pragma unroll
    for (int g = 0; g < NG; g++) {
        float4 o;
        float* oo = (float*)&o;
        #pragma unroll
        for (int j = 0; j < 4; j++) {
            const float* p = xb + (size_t)(4 * g + j) * HW;
            oo[j] = w00 * p[r0 + tx0] + w01 * p[r0 + tx1]
                  + w10 * p[r1 + tx0] + w11 * p[r1 + tx1];
        }
        ob[(size_t)g * HW2] = o;
    }
}

// -------- kernel 2: upsample a 2ch 512 field ->1024, *2, interleaved float2 ----
__global__ void __launch_bounds__(256) k_up_res(const float* __restrict__ ext,
                                                int src_sel, int dst_sel) {
    int idx = blockIdx.x * blockDim.x + threadIdx.x;
    if (idx >= BB * H2 * (W2 / 4)) return;
    int xq = idx & (W2 / 4 - 1);
    int yy = (idx >> 8) & (H2 - 1);
    int b  = idx >> 18;
    int m = 2 * xq;
    int mm1 = max(m - 1, 0), mp2 = min(m + 2, WW - 1);
    float a00 = (m == 0) ? 0.f : 0.25f,  a01 = (m == 0) ? 1.f : 0.75f;
    float a30 = (m == WW - 2) ? 1.f : 0.75f, a31 = (m == WW - 2) ? 0.f : 0.25f;
    int ty0, ty1; float wy0, wy1;
    up_taps(yy, HH, ty0, ty1, wy0, wy1);
    int r0 = ty0 * WW, r1 = ty1 * WW;

    const float* src = (src_sel == 0) ? ext : ((src_sel == 1) ? g_adj : g_newres);
    const float* p0 = src + (size_t)b * 2 * HW;
    const float* p1 = p0 + HW;
    float ox[4], oy[4];
    {
        float s0 = p0[r0 + mm1]   * wy0 + p0[r1 + mm1]   * wy1;
        float s1 = p0[r0 + m]     * wy0 + p0[r1 + m]     * wy1;
        float s2 = p0[r0 + m + 1] * wy0 + p0[r1 + m + 1] * wy1;
        float s3 = p0[r0 + mp2]   * wy0 + p0[r1 + mp2]   * wy1;
        ox[0] = a00 * s0 + a01 * s1;  ox[1] = 0.75f * s1 + 0.25f * s2;
        ox[2] = 0.25f * s1 + 0.75f * s2;  ox[3] = a30 * s2 + a31 * s3;
    }
    {
        float s0 = p1[r0 + mm1]   * wy0 + p1[r1 + mm1]   * wy1;
        float s1 = p1[r0 + m]     * wy0 + p1[r1 + m]     * wy1;
        float s2 = p1[r0 + m + 1] * wy0 + p1[r1 + m + 1] * wy1;
        float s3 = p1[r0 + mp2]   * wy0 + p1[r1 + mp2]   * wy1;
        oy[0] = a00 * s0 + a01 * s1;  oy[1] = 0.75f * s1 + 0.25f * s2;
        oy[2] = 0.25f * s1 + 0.75f * s2;  oy[3] = a30 * s2 + a31 * s3;
    }
    float2* dst = (dst_sel == 0) ? g_a1024 : ((dst_sel == 1) ? g_b1024 : g_nr1024);
    float4* ob = (float4*)(dst + (size_t)b * HW2 + (size_t)yy * W2 + 4 * xq);
    ob[0] = make_float4(2.f * ox[0], 2.f * oy[0], 2.f * ox[1], 2.f * oy[1]);
    ob[1] = make_float4(2.f * ox[2], 2.f * oy[2], 2.f * ox[3], 2.f * oy[3]);
}

// -------- fused: reg gather tables -> 4ch-at-a-time warp+downsample --------
__global__ void __launch_bounds__(256) k_warpdown(
        float* __restrict__ out, int field_sel, int to_final) {
    __shared__ float4 s_w[TWNW];
    int b = blockIdx.z;
    int x0 = blockIdx.x * TSW, y0 = blockIdx.y * TSW;
    int gx0 = 2 * x0 - 1, gy0 = 2 * y0 - 1;
    int tid = threadIdx.x;

    const float2* fld = ((field_sel == 0) ? g_a1024 : g_nr1024) + (size_t)b * HW2;

    float4   rw[NPOS];
    unsigned rpk[NPOS];
    #pragma unroll
    for (int k = 0; k < NPOS; k++) {
        int i = tid + 256 * k;
        if (i < TWNW) {
            int r = i / TWW, cc = i - r * TWW;
            int Y = min(max(gy0 + r, 0), H2 - 1);
            int X = min(max(gx0 + cc, 0), W2 - 1);
            float2 f = fld[Y * W2 + X];
            float sx = (float)(gx0 + cc) + f.x;
            float sy = (float)(gy0 + r) + f.y;
            float xf = floorf(sx), yf = floorf(sy);
            float fx = sx - xf, fy = sy - yf;
            int ix0 = (int)xf, iy0 = (int)yf;
            bool bx0 = (unsigned)ix0 < W2, bx1 = (unsigned)(ix0 + 1) < W2;
            bool by0 = (unsigned)iy0 < H2, by1 = (unsigned)(iy0 + 1) < H2;
            float wx0 = bx0 ? (1.f - fx) : 0.f, wx1 = bx1 ? fx : 0.f;
            float wy0 = by0 ? (1.f - fy) : 0.f, wy1 = by1 ? fy : 0.f;
            rw[k] = make_float4(wy0 * wx0, wy0 * wx1, wy1 * wx0, wy1 * wx1);
            int cx0 = min(max(ix0, 0), W2 - 1), cx1 = min(max(ix0 + 1, 0), W2 - 1);
            int cy0 = min(max(iy0, 0), H2 - 1), cy1 = min(max(iy0 + 1, 0), H2 - 1);
            rpk[k] = (unsigned)(cy0 * W2 + cx0)
                   | ((unsigned)(cx1 - cx0) << 20)
                   | ((unsigned)(cy1 - cy0) << 21);
        }
    }

    const float4* img = g_up16 + (size_t)b * NG * HW2;
    float* dstb = to_final ? (out + ((size_t)b * 2 * NF + NF) * HW)
                           : (g_warped + (size_t)b * NF * HW);
    int lx = tid & (TSW - 1), ly = tid >> 4;
    int yy = y0 + ly, xx = x0 + lx;
    float invsy = (yy == 0 || yy == HH - 1) ? (1.f / 1.75f) : 0.5f;
    float invsx = (xx == 0 || xx == WW - 1) ? (1.f / 1.75f) : 0.5f;
    float wyv[4], wxv[4];
    #pragma unroll
    for (int t = 0; t < 4; t++) {
        wyv[t] = ((unsigned)(gy0 + 2 * ly + t) < H2) ? dbase(t) * invsy : 0.f;
        wxv[t] = ((unsigned)(gx0 + 2 * lx + t) < W2) ? dbase(t) * invsx : 0.f;
    }
    int sbase = (2 * ly) * TWW + 2 * lx;
    int opix = yy * WW + xx;

    for (int g = 0; g < NG; g++) {
        const float4* p = img + (size_t)g * HW2;
        #pragma unroll
        for (int k = 0; k < NPOS; k++) {
            int i = tid + 256 * k;
            if (i < TWNW) {
                unsigned pk = rpk[k];
                float4 w = rw[k];
                int o00 = (int)(pk & 0xFFFFFu);
                int dx  = (int)((pk >> 20) & 1u);
                int o10 = o00 + (int)((pk >> 11) & 1024u);
                float4 v00 = p[o00], v01 = p[o00 + dx];
                float4 v10 = p[o10], v11 = p[o10 + dx];
                float4 acc;
                acc.x = w.x * v00.x + w.y * v01.x + w.z * v10.x + w.w * v11.x;
                acc.y = w.x * v00.y + w.y * v01.y + w.z * v10.y + w.w * v11.y;
                acc.z = w.x * v00.z + w.y * v01.z + w.z * v10.z + w.w * v11.z;
                acc.w = w.x * v00.w + w.y * v01.w + w.z * v10.w + w.w * v11.w;
                s_w[i] = acc;
            }
        }
        __syncthreads();
        float4 acc = make_float4(0.f, 0.f, 0.f, 0.f);
        #pragma unroll
        for (int ty = 0; ty < 4; ty++) {
            const float4* sr = s_w + sbase + ty * TWW;
            float4 rowv = make_float4(0.f, 0.f, 0.f, 0.f);
            #pragma unroll
            for (int tx = 0; tx < 4; tx++) {
                float4 v = sr[tx];
                float w = wxv[tx];
                rowv.x += w * v.x; rowv.y += w * v.y;
                rowv.z += w * v.z; rowv.w += w * v.w;
            }
            float w = wyv[ty];
            acc.x += w * rowv.x; acc.y += w * rowv.y;
            acc.z += w * rowv.z; acc.w += w * rowv.w;
        }
        dstb[(size_t)(4 * g + 0) * HW + opix] = acc.x;
        dstb[(size_t)(4 * g + 1) * HW + opix] = acc.y;
        dstb[(size_t)(4 * g + 2) * HW + opix] = acc.z;
        dstb[(size_t)(4 * g + 3) * HW + opix] = acc.w;
        __syncthreads();
    }
}

// -------- 3x3 conv 50->2: vertical strip, rolling register window ------------
// thread = one column x, CR output rows. 187 LDG/pixel instead of 450.
__global__ void __launch_bounds__(256) k_conv(
        const float* __restrict__ x, const float* __restrict__ res,
        const float* __restrict__ Wc, const float* __restrict__ bias,
        float* __restrict__ out) {
    __shared__ float sw[2 * CINc * 9];
    for (int i = threadIdx.x; i < 2 * CINc * 9; i += blockDim.x) sw[i] = Wc[i];
    __syncthreads();
    int idx = blockIdx.x * blockDim.x + threadIdx.x;
    if (idx >= BB * (HH / CR) * WW) return;
    int xx = idx & (WW - 1);
    int ys = (idx >> 9) & (HH / CR - 1);
    int b  = idx >> 15;
    int y0 = ys * CR;

    const float* xb = x + (size_t)b * 2 * NF * HW;
    const float* wb = g_warped + (size_t)b * NF * HW;
    const float* rb = res + (size_t)b * 2 * HW;
    bool lok = (xx > 0), rok = (xx < WW - 1);

    float a0[CR], a1[CR];
    #pragma unroll
    for (int k = 0; k < CR; k++) { a0[k] = 0.f; a1[k] = 0.f; }

    for (int c = 0; c < CINc; c++) {
        const float* p = (c < 32) ? (xb + (size_t)c * HW)
                       : (c < 48) ? (wb + (size_t)(c - 32) * HW)
                                  : (rb + (size_t)(c - 48) * HW);
        const float* q = sw + c * 9;            // out-channel 0 weights
        const float* u = sw + CINc * 9 + c * 9; // out-channel 1 weights
        float q0 = q[0], q1 = q[1], q2 = q[2], q3 = q[3], q4 = q[4];
        float q5 = q[5], q6 = q[6], q7 = q[7], q8 = q[8];
        float u0 = u[0], u1 = u[1], u2 = u[2], u3 = u[3], u4 = u[4];
        float u5 = u[5], u6 = u[6], u7 = u[7], u8 = u[8];

        float vm[3], v0[3], vp[3];   // rolling ring of 3 rows
        #pragma unroll
        for (int r = 0; r < CR + 2; r++) {
            int yr = y0 - 1 + r;
            int slot = r % 3;
            if ((unsigned)yr < HH) {
                int ro = yr * WW + xx;
                vm[slot] = lok ? p[ro - 1] : 0.f;
                v0[slot] = p[ro];
                vp[slot] = rok ? p[ro + 1] : 0.f;
            } else {
                vm[slot] = 0.f; v0[slot] = 0.f; vp[slot] = 0.f;
            }
            if (r >= 2) {
                int k = r - 2;                   // output row
                int st = (r - 2) % 3, sm = (r - 1) % 3, sb = r % 3;
                a0[k] += vm[st] * q0 + v0[st] * q1 + vp[st] * q2
                       + vm[sm] * q3 + v0[sm] * q4 + vp[sm] * q5
                       + vm[sb] * q6 + v0[sb] * q7 + vp[sb] * q8;
                a1[k] += vm[st] * u0 + v0[st] * u1 + vp[st] * u2
                       + vm[sm] * u3 + v0[sm] * u4 + vp[sm] * u5
                       + vm[sb] * u6 + v0[sb] * u7 + vp[sb] * u8;
            }
        }
    }

    float b0 = bias[0], b1 = bias[1];
    float* o = g_adj + (size_t)b * 2 * HW;
    #pragma unroll
    for (int k = 0; k < CR; k++) {
        int pc = (y0 + k) * WW + xx;
        o[pc]      = a0[k] + b0;
        o[HW + pc] = a1[k] + b1;
    }
    // pass-through: out[b][0..15] = x[b][0..15]
    float* ob = out + (size_t)b * 2 * NF * HW;
    #pragma unroll
    for (int c = 0; c < NF; c++) {
        const float* ps = xb + (size_t)c * HW;
        float* pd = ob + (size_t)c * HW;
        #pragma unroll
        for (int k = 0; k < CR; k++) {
            int pc = (y0 + k) * WW + xx;
            pd[pc] = ps[pc];
        }
    }
}

// -------- fused: warp a1024 by b1024 (tables) -> downsample*0.5 + adj ----------
__global__ void __launch_bounds__(256) k_combine() {
    __shared__ float2 s_w[TWNW];
    int b = blockIdx.z;
    int x0 = blockIdx.x * TSW, y0 = blockIdx.y * TSW;
    int gx0 = 2 * x0 - 1, gy0 = 2 * y0 - 1;
    int tid = threadIdx.x;

    const float2* bf = g_b1024 + (size_t)b * HW2;
    const float2* af = g_a1024 + (size_t)b * HW2;

    #pragma unroll
    for (int k = 0; k < NPOS; k++) {
        int i = tid + 256 * k;
        if (i < TWNW) {
            int r = i / TWW, cc = i - r * TWW;
            int Y = min(max(gy0 + r, 0), H2 - 1);
            int X = min(max(gx0 + cc, 0), W2 - 1);
            float2 f = bf[Y * W2 + X];
            float sx = (float)(gx0 + cc) + f.x;
            float sy = (float)(gy0 + r) + f.y;
            float xf = floorf(sx), yf = floorf(sy);
            float fx = sx - xf, fy = sy - yf;
            int ix0 = (int)xf, iy0 = (int)yf;
            bool bx0 = (unsigned)ix0 < W2, bx1 = (unsigned)(ix0 + 1) < W2;
            bool by0 = (unsigned)iy0 < H2, by1 = (unsigned)(iy0 + 1) < H2;
            float wx0 = bx0 ? (1.f - fx) : 0.f, wx1 = bx1 ? fx : 0.f;
            float wy0 = by0 ? (1.f - fy) : 0.f, wy1 = by1 ? fy : 0.f;
            float w00 = wy0 * wx0, w01 = wy0 * wx1, w10 = wy1 * wx0, w11 = wy1 * wx1;
            int cx0 = min(max(ix0, 0), W2 - 1), cx1 = min(max(ix0 + 1, 0), W2 - 1);
            int cy0 = min(max(iy0, 0), H2 - 1), cy1 = min(max(iy0 + 1, 0), H2 - 1);
            int o00 = cy0 * W2 + cx0;
            int dxo = cx1 - cx0;
            int o10 = o00 + (cy1 - cy0) * W2;
            float2 v00 = af[o00], v01 = af[o00 + dxo];
            float2 v10 = af[o10], v11 = af[o10 + dxo];
            s_w[i] = make_float2(
                w00 * v00.x + w01 * v01.x + w10 * v10.x + w11 * v11.x,
                w00 * v00.y + w01 * v01.y + w10 * v10.y + w11 * v11.y);
        }
    }
    __syncthreads();

    int lx = tid & (TSW - 1), ly = tid >> 4;
    int yy = y0 + ly, xx = x0 + lx;
    float invsy = (yy == 0 || yy == HH - 1) ? (1.f / 1.75f) : 0.5f;
    float invsx = (xx == 0 || xx == WW - 1) ? (1.f / 1.75f) : 0.5f;
    float wyv[4], wxv[4];
    #pragma unroll
    for (int t = 0; t < 4; t++) {
        wyv[t] = ((unsigned)(gy0 + 2 * ly + t) < H2) ? dbase(t) * invsy : 0.f;
        wxv[t] = ((unsigned)(gx0 + 2 * lx + t) < W2) ? dbase(t) * invsx : 0.f;
    }
    int sbase = (2 * ly) * TWW + 2 * lx;
    float accx = 0.f, accy = 0.f;
    #pragma unroll
    for (int ty = 0; ty < 4; ty++) {
        const float2* sr = s_w + sbase + ty * TWW;
        float rx = wxv[0] * sr[0].x + wxv[1] * sr[1].x + wxv[2] * sr[2].x + wxv[3] * sr[3].x;
        float ry = wxv[0] * sr[0].y + wxv[1] * sr[1].y + wxv[2] * sr[2].y + wxv[3] * sr[3].y;
        accx += wyv[ty] * rx;
        accy += wyv[ty] * ry;
    }
    int p = yy * WW + xx;
    const float* ad = g_adj + (size_t)b * 2 * HW;
    float* nr = g_newres + (size_t)b * 2 * HW;
    nr[p]      = ad[p]      + 0.5f * accx;
    nr[HW + p] = ad[HW + p] + 0.5f * accy;
}

// -------- launch --------
extern "C" void kernel_launch(void* const* d_in, const int* in_sizes, int n_in,
                              void* d_out, int out_size) {
    const float* x    = (const float*)d_in[0];
    const float* res  = (const float*)d_in[1];
    const float* Wc   = (const float*)d_in[2];
    const float* bias = (const float*)d_in[3];
    float* out = (float*)d_out;

    const int T = 256;
    dim3 gu1((BB * HW2 + T - 1) / T);
    dim3 gu((BB * H2 * (W2 / 4) + T - 1) / T);
    dim3 gcv((BB * (HH / CR) * WW + T - 1) / T);
    dim3 gw(HH / TSW, WW / TSW, BB);

    k_up_img<<<gu1, T>>>(x);                      // tgt -> g_up16 (packed x4)
    k_up_res<<<gu, T>>>(res, 0, 0);               // res -> g_a1024 (*2)
    k_warpdown<<<gw, T>>>(nullptr, 0, 0);         // warp by a1024 -> g_warped
    k_conv<<<gcv, T>>>(x, res, Wc, bias, out);    // adj + src pass-through
    k_up_res<<<gu, T>>>(nullptr, 1, 1);           // adj -> g_b1024 (*2)
    k_combine<<<gw, T>>>();                       // -> g_newres
    k_up_res<<<gu, T>>>(nullptr, 2, 2);           // new_res -> g_nr1024 (*2)
    k_warpdown<<<gw, T>>>(out, 1, 1);             // warp by nr1024 -> out[16..31]
}